// round 1
// baseline (speedup 1.0000x reference)
#include <cuda_runtime.h>
#include <cuda_bf16.h>
#include <cstdint>

// LSTMDecoder: 48 sequential steps of
//   z = h @ W_hh^T + (b_ih + b_hh)   (M=2048, N=4096, K=1024)
//   i,f,g,o gates -> c,h update -> out[n][j][t] = h_new
//
// Strategy: one fused kernel per step (stream-ordered launches give the
// cross-step dependency). tf32 mma.sync GEMM, fp32 accumulate, fused gate
// epilogue. State (h ping-pong, c, bias) in __device__ statics (no allocs).

#define HDIM 1024
#define NBATCH 2048
#define LSTEPS 48
#define BM 128          // batch rows per block
#define BJ 32           // H columns per block (-> 128 z-columns: 4 gates x 32)
#define BN 128          // z columns per block
#define BK 32           // K tile
#define APAD 36         // padded smem row stride (floats), 36%4==0 for float4 st
#define ZSTRIDE 132     // padded z smem row stride
#define SMEM_BYTES (4 * BM * APAD * 4)   // 2xA + 2xB buffers = 73728 B

__device__ float g_h[2][NBATCH * HDIM];  // h ping-pong
__device__ float g_c[NBATCH * HDIM];     // cell state
__device__ float g_bias[4 * HDIM];       // b_ih + b_hh

__device__ __forceinline__ float tf32r(float x) {
    uint32_t u;
    asm("cvt.rna.tf32.f32 %0, %1;" : "=r"(u) : "f"(x));
    return __uint_as_float(u);
}

__device__ __forceinline__ void mma_tf32(float* c,
                                         uint32_t a0, uint32_t a1, uint32_t a2, uint32_t a3,
                                         uint32_t b0, uint32_t b1) {
    asm("mma.sync.aligned.m16n8k8.row.col.f32.tf32.tf32.f32 "
        "{%0,%1,%2,%3}, {%4,%5,%6,%7}, {%8,%9}, {%0,%1,%2,%3};"
        : "+f"(c[0]), "+f"(c[1]), "+f"(c[2]), "+f"(c[3])
        : "r"(a0), "r"(a1), "r"(a2), "r"(a3), "r"(b0), "r"(b1));
}

__device__ __forceinline__ float fast_sigmoid(float x) {
    return 1.0f / (1.0f + __expf(-x));
}
__device__ __forceinline__ float fast_tanh(float x) {
    return 2.0f / (1.0f + __expf(-2.0f * x)) - 1.0f;
}

__global__ void bias_kernel(const float* __restrict__ b_ih, const float* __restrict__ b_hh) {
    int i = blockIdx.x * blockDim.x + threadIdx.x;
    if (i < 4 * HDIM) g_bias[i] = b_ih[i] + b_hh[i];
}

__global__ __launch_bounds__(256, 2)
void lstm_step(const float* __restrict__ h_in, const float* __restrict__ W,
               float* __restrict__ out, int t) {
    extern __shared__ float sm[];
    float* As = sm;                    // [2][BM][APAD]
    float* Bs = sm + 2 * BM * APAD;    // [2][BN][APAD]

    const float* __restrict__ h_src = (t == 0) ? h_in : g_h[(t - 1) & 1];
    float* __restrict__ h_dst = g_h[t & 1];

    const int tid  = threadIdx.x;
    const int warp = tid >> 5, lane = tid & 31;
    const int wm = warp >> 1, wn = warp & 1;      // 4 x 2 warp grid
    const int gid = lane >> 2, tig = lane & 3;
    const int m0 = blockIdx.x * BM;
    const int j0 = blockIdx.y * BJ;

    float acc[2][8][4];
#pragma unroll
    for (int im = 0; im < 2; im++)
#pragma unroll
        for (int in_ = 0; in_ < 8; in_++)
#pragma unroll
            for (int q = 0; q < 4; q++) acc[im][in_][q] = 0.0f;

    // global load mapping: 256 threads, 4 passes of 32 rows; 8 float4 per row
    const int lrow = tid >> 3;           // 0..31
    const int lcol = (tid & 7) * 4;      // 0..28

    float4 ar[4], br[4];

    auto loadTiles = [&](int k0) {
#pragma unroll
        for (int p = 0; p < 4; p++) {
            // A rows: batch m0 + p*32 + lrow
            ar[p] = *(const float4*)&h_src[(size_t)(m0 + p * 32 + lrow) * HDIM + k0 + lcol];
            // B rows: z-col r = p*32 + lrow -> gate p, jj = lrow
            br[p] = *(const float4*)&W[(size_t)(p * HDIM + j0 + lrow) * HDIM + k0 + lcol];
        }
    };
    auto storeTiles = [&](int buf) {
        float* Ab = As + buf * BM * APAD;
        float* Bb = Bs + buf * BN * APAD;
#pragma unroll
        for (int p = 0; p < 4; p++) {
            int r = p * 32 + lrow;
            float4 a = ar[p];
            a.x = tf32r(a.x); a.y = tf32r(a.y); a.z = tf32r(a.z); a.w = tf32r(a.w);
            *(float4*)&Ab[r * APAD + lcol] = a;
            float4 b = br[p];
            b.x = tf32r(b.x); b.y = tf32r(b.y); b.z = tf32r(b.z); b.w = tf32r(b.w);
            *(float4*)&Bb[r * APAD + lcol] = b;
        }
    };
    auto computeTile = [&](int buf) {
        const float* Ab = As + buf * BM * APAD;
        const float* Bb = Bs + buf * BN * APAD;
#pragma unroll
        for (int kk = 0; kk < 4; kk++) {
            int kb = kk * 8;
            uint32_t af[2][4], bf[8][2];
#pragma unroll
            for (int im = 0; im < 2; im++) {
                int r = wm * 32 + im * 16 + gid;
                af[im][0] = __float_as_uint(Ab[r * APAD + kb + tig]);
                af[im][1] = __float_as_uint(Ab[(r + 8) * APAD + kb + tig]);
                af[im][2] = __float_as_uint(Ab[r * APAD + kb + tig + 4]);
                af[im][3] = __float_as_uint(Ab[(r + 8) * APAD + kb + tig + 4]);
            }
#pragma unroll
            for (int in_ = 0; in_ < 8; in_++) {
                int n = wn * 64 + in_ * 8 + gid;
                bf[in_][0] = __float_as_uint(Bb[n * APAD + kb + tig]);
                bf[in_][1] = __float_as_uint(Bb[n * APAD + kb + tig + 4]);
            }
#pragma unroll
            for (int im = 0; im < 2; im++)
#pragma unroll
                for (int in_ = 0; in_ < 8; in_++)
                    mma_tf32(acc[im][in_], af[im][0], af[im][1], af[im][2], af[im][3],
                             bf[in_][0], bf[in_][1]);
        }
    };

    // mainloop: double-buffered smem, register-staged global prefetch
    loadTiles(0);
    storeTiles(0);
    __syncthreads();
#pragma unroll 1
    for (int kt = 0; kt < HDIM / BK; kt++) {
        int cur = kt & 1;
        if (kt + 1 < HDIM / BK) loadTiles((kt + 1) * BK);
        computeTile(cur);
        __syncthreads();
        if (kt + 1 < HDIM / BK) {
            storeTiles(cur ^ 1);
            __syncthreads();
        }
    }
    __syncthreads();  // everyone done with As/Bs before reuse as z

    // stage z tile (128 x 128) through smem so each thread can gather 4 gates
    float* zs = sm;  // 128 * ZSTRIDE floats = 67584 B <= SMEM_BYTES
#pragma unroll
    for (int im = 0; im < 2; im++) {
#pragma unroll
        for (int in_ = 0; in_ < 8; in_++) {
            int r = wm * 32 + im * 16 + gid;
            int c = wn * 64 + in_ * 8 + tig * 2;
            zs[r * ZSTRIDE + c]           = acc[im][in_][0];
            zs[r * ZSTRIDE + c + 1]       = acc[im][in_][1];
            zs[(r + 8) * ZSTRIDE + c]     = acc[im][in_][2];
            zs[(r + 8) * ZSTRIDE + c + 1] = acc[im][in_][3];
        }
    }
    __syncthreads();

    const bool first = (t == 0);
#pragma unroll
    for (int e = 0; e < 16; e++) {
        int idx = e * 256 + tid;     // 0..4095
        int m = idx >> 5;            // 0..127
        int jj = idx & 31;
        int gm = m0 + m;
        int j = j0 + jj;
        float zi = zs[m * ZSTRIDE + jj]       + g_bias[j];
        float zf = zs[m * ZSTRIDE + 32 + jj]  + g_bias[HDIM + j];
        float zg = zs[m * ZSTRIDE + 64 + jj]  + g_bias[2 * HDIM + j];
        float zo = zs[m * ZSTRIDE + 96 + jj]  + g_bias[3 * HDIM + j];

        float ig = fast_sigmoid(zi);
        float fg = fast_sigmoid(zf);
        float gg = fast_tanh(zg);
        float og = fast_sigmoid(zo);

        size_t sidx = (size_t)gm * HDIM + j;
        float cold = first ? 0.0f : g_c[sidx];
        float cnew = fg * cold + ig * gg;
        float hnew = og * fast_tanh(cnew);

        g_c[sidx] = cnew;
        h_dst[sidx] = hnew;
        out[sidx * LSTEPS + t] = hnew;
    }
}

extern "C" void kernel_launch(void* const* d_in, const int* in_sizes, int n_in,
                              void* d_out, int out_size) {
    const float* h_in = (const float*)d_in[0];
    const float* W    = (const float*)d_in[1];
    const float* b_ih = (const float*)d_in[2];
    const float* b_hh = (const float*)d_in[3];
    float* out = (float*)d_out;

    cudaFuncSetAttribute(lstm_step, cudaFuncAttributeMaxDynamicSharedMemorySize, SMEM_BYTES);

    bias_kernel<<<16, 256>>>(b_ih, b_hh);

    dim3 grid(NBATCH / BM, HDIM / BJ);  // 16 x 32 = 512 blocks
    for (int t = 0; t < LSTEPS; t++) {
        lstm_step<<<grid, 256, SMEM_BYTES>>>(h_in, W, out, t);
    }
}

// round 3
// speedup vs baseline: 1.5454x; 1.5454x over previous
#include <cuda_runtime.h>
#include <cstdint>

// LSTMDecoder on GB300 (harness targets plain sm_103 -> no tcgen05; use
// Ampere-style mma.sync tf32). 48 sequential steps of
//   z = h @ W^T + bias (M=2048, N=4096, K=1024), fused i/f/g/o gate epilogue.
// cp.async 3-stage pipeline, SW128-swizzled smem, 64x64 warp tiles,
// bias folded into accumulator init, shfl-paired gate fusion,
// contiguous per-step output + final transpose.

#define HDIM   1024
#define NBATCH 2048
#define LSTEPS 48
#define TM     128          // CTA rows (batch)
#define TN     256          // CTA z-cols (= 64 j x 4 gates, interleaved j*4+g)
#define TJ     64
#define BK     32           // K per stage (32 f32 = 128B rows)
#define NSTAGE 3
#define KTILES (HDIM / BK)  // 32

#define SM_BIAS 0                                  // 256 floats
#define SM_PIPE 1024
#define A_BYTES (TM * BK * 4)                      // 16384
#define B_BYTES (TN * BK * 4)                      // 32768
#define STAGE_BYTES (A_BYTES + B_BYTES)            // 49152
#define SMEM_TOTAL (SM_PIPE + NSTAGE * STAGE_BYTES)// 148480

#define EPS 65                                     // epilogue j-stride (padded)

#define SWZ(o) ((o) ^ (((o) >> 3) & 0x70))

__device__ float g_h[2][NBATCH * HDIM];          // tf32-rounded h ping-pong
__device__ float g_c[NBATCH * HDIM];             // cell state (fp32)
__device__ float g_Wr[4 * HDIM * HDIM];          // reordered+rounded W: row j*4+g
__device__ float g_biasr[4 * HDIM];              // reordered bias
__device__ float g_hist[LSTEPS][NBATCH * HDIM];  // full-precision h history

// ---------- helpers ----------
__device__ __forceinline__ uint32_t smem_u32(const void* p) {
    uint32_t a;
    asm("{ .reg .u64 t; cvta.to.shared.u64 t, %1; cvt.u32.u64 %0, t; }" : "=r"(a) : "l"(p));
    return a;
}
__device__ __forceinline__ float tf32r(float x) {
    uint32_t u;
    asm("cvt.rna.tf32.f32 %0, %1;" : "=r"(u) : "f"(x));
    return __uint_as_float(u);
}
__device__ __forceinline__ void cpa16(uint32_t dst, const void* src) {
    asm volatile("cp.async.cg.shared.global [%0], [%1], 16;" :: "r"(dst), "l"(src));
}
#define CP_COMMIT() asm volatile("cp.async.commit_group;" ::: "memory")
#define CP_WAIT1()  asm volatile("cp.async.wait_group 1;" ::: "memory")

__device__ __forceinline__ uint32_t lds32(uint32_t a) {
    uint32_t v;
    asm("ld.shared.b32 %0, [%1];" : "=r"(v) : "r"(a));
    return v;
}
__device__ __forceinline__ void mma8(float* c, const uint32_t* a, const uint32_t* b) {
    asm("mma.sync.aligned.m16n8k8.row.col.f32.tf32.tf32.f32 "
        "{%0,%1,%2,%3}, {%4,%5,%6,%7}, {%8,%9}, {%0,%1,%2,%3};"
        : "+f"(c[0]), "+f"(c[1]), "+f"(c[2]), "+f"(c[3])
        : "r"(a[0]), "r"(a[1]), "r"(a[2]), "r"(a[3]), "r"(b[0]), "r"(b[1]));
}
__device__ __forceinline__ float sigm(float x) {
    return __fdividef(1.0f, 1.0f + __expf(-x));
}
__device__ __forceinline__ float tanh_(float x) {
    return __fdividef(2.0f, 1.0f + __expf(-2.0f * x)) - 1.0f;
}

// ---------- prep kernels ----------
__global__ void prep_h(const float* __restrict__ h_in) {
    int i = blockIdx.x * 256 + threadIdx.x;
    float4 v = ((const float4*)h_in)[i];
    v.x = tf32r(v.x); v.y = tf32r(v.y); v.z = tf32r(v.z); v.w = tf32r(v.w);
    ((float4*)g_h[0])[i] = v;
}
__global__ void prep_w(const float* __restrict__ W) {
    int idx = blockIdx.x * 256 + threadIdx.x;  // 4096 rows x 256 float4
    int rn = idx >> 8, k4 = idx & 255;
    int j = rn >> 2, g = rn & 3;
    float4 v = ((const float4*)W)[(size_t)(g * HDIM + j) * (HDIM / 4) + k4];
    v.x = tf32r(v.x); v.y = tf32r(v.y); v.z = tf32r(v.z); v.w = tf32r(v.w);
    ((float4*)g_Wr)[(size_t)rn * (HDIM / 4) + k4] = v;
}
__global__ void prep_bias(const float* __restrict__ bi, const float* __restrict__ bh) {
    int i = blockIdx.x * 256 + threadIdx.x;
    if (i < 4 * HDIM) {
        int j = i >> 2, g = i & 3;
        g_biasr[i] = bi[g * HDIM + j] + bh[g * HDIM + j];
    }
}

// ---------- main step kernel ----------
__global__ __launch_bounds__(256, 1)
void lstm_step(int t) {
    extern __shared__ char smc[];
    float* sbias = (float*)(smc + SM_BIAS);
    const uint32_t smb = smem_u32(smc);

    const int tid = threadIdx.x;
    const int w = tid >> 5, lane = tid & 31;
    const int gid = lane >> 2, tig = lane & 3;
    const int wm = w >> 2, wn = w & 3;          // 2 x 4 warp grid, 64x64 tiles
    const int m0 = blockIdx.x * TM;
    const int n0 = blockIdx.y * TN;
    const int jblk = blockIdx.y * TJ;

    const float* __restrict__ hsrc = g_h[t & 1];
    float* __restrict__ hdst = g_h[(t + 1) & 1];
    float* __restrict__ hist = g_hist[t];

    sbias[tid] = g_biasr[n0 + tid];

    auto load_tile = [&](int kt, int s) {
        const uint32_t abase = smb + SM_PIPE + s * STAGE_BYTES;
        const uint32_t bbase = abase + A_BYTES;
        const float* asrc = hsrc + (size_t)m0 * HDIM + kt * BK;
        const float* bsrc = g_Wr + (size_t)n0 * HDIM + kt * BK;
#pragma unroll
        for (int p = 0; p < 4; p++) {           // A: 128 rows x 128B
            int idx = tid + p * 256;
            int row = idx >> 3, ch = idx & 7;
            uint32_t off = (uint32_t)(row * 128 + ch * 16);
            cpa16(abase + SWZ(off), asrc + (size_t)row * HDIM + ch * 4);
        }
#pragma unroll
        for (int p = 0; p < 8; p++) {           // B: 256 rows x 128B
            int idx = tid + p * 256;
            int row = idx >> 3, ch = idx & 7;
            uint32_t off = (uint32_t)(row * 128 + ch * 16);
            cpa16(bbase + SWZ(off), bsrc + (size_t)row * HDIM + ch * 4);
        }
    };

    load_tile(0, 0); CP_COMMIT();
    load_tile(1, 1); CP_COMMIT();
    __syncthreads();  // sbias visible

    // accumulators, bias folded in (col of c0/c2 = base, c1/c3 = base+1)
    float acc[4][8][4];
#pragma unroll
    for (int mf = 0; mf < 4; mf++)
#pragma unroll
        for (int nf = 0; nf < 8; nf++) {
            int c = wn * 64 + nf * 8 + 2 * tig;
            float b0 = sbias[c], b1 = sbias[c + 1];
            acc[mf][nf][0] = b0; acc[mf][nf][1] = b1;
            acc[mf][nf][2] = b0; acc[mf][nf][3] = b1;
        }

    // per-thread smem row offsets (swizzle-chunk handled per-kk via XOR)
    uint32_t arow[4], brow[8];
#pragma unroll
    for (int mf = 0; mf < 4; mf++) arow[mf] = (uint32_t)(wm * 64 + mf * 16 + gid) * 128;
#pragma unroll
    for (int nf = 0; nf < 8; nf++) brow[nf] = (uint32_t)(wn * 64 + nf * 8 + gid) * 128;
    const uint32_t t4 = (uint32_t)tig * 4;

#pragma unroll 1
    for (int kt = 0; kt < KTILES; kt++) {
        const int s = kt % NSTAGE;
        CP_WAIT1();
        __syncthreads();
        if (kt + 2 < KTILES) load_tile(kt + 2, (kt + 2) % NSTAGE);
        CP_COMMIT();

        const uint32_t aB = smb + SM_PIPE + s * STAGE_BYTES;
        const uint32_t bB = aB + A_BYTES;
#pragma unroll
        for (int kk = 0; kk < 4; kk++) {
            const uint32_t x0 = (uint32_t)((2 * kk) ^ gid) * 16 + t4;
            const uint32_t x1 = (uint32_t)((2 * kk + 1) ^ gid) * 16 + t4;
            uint32_t af[4][4], bf[8][2];
#pragma unroll
            for (int mf = 0; mf < 4; mf++) {
                uint32_t a0 = aB + arow[mf] + x0;
                uint32_t a1 = aB + arow[mf] + x1;
                af[mf][0] = lds32(a0);
                af[mf][1] = lds32(a0 + 1024);   // row +8
                af[mf][2] = lds32(a1);          // k +4
                af[mf][3] = lds32(a1 + 1024);
            }
#pragma unroll
            for (int nf = 0; nf < 8; nf++) {
                bf[nf][0] = lds32(bB + brow[nf] + x0);
                bf[nf][1] = lds32(bB + brow[nf] + x1);
            }
#pragma unroll
            for (int mf = 0; mf < 4; mf++)
#pragma unroll
                for (int nf = 0; nf < 8; nf++)
                    mma8(acc[mf][nf], af[mf], bf[nf]);
        }
    }
    __syncthreads();  // all MMAs done before smem reuse

    // ---- epilogue: shfl-pair gate fusion -> smem staging ----
    float* P  = (float*)(smc + SM_PIPE);           // i*g
    float* F  = P + TM * EPS;                      // f
    float* OG = F + TM * EPS;                      // o
    const int odd = tig & 1;

#pragma unroll
    for (int mf = 0; mf < 4; mf++)
#pragma unroll
        for (int nf = 0; nf < 8; nf++) {
            float c0 = acc[mf][nf][0], c1 = acc[mf][nf][1];
            float c2 = acc[mf][nf][2], c3 = acc[mf][nf][3];
            float e0 = __shfl_xor_sync(0xFFFFFFFFu, c0, 1);
            float e1 = __shfl_xor_sync(0xFFFFFFFFu, c1, 1);
            float e2 = __shfl_xor_sync(0xFFFFFFFFu, c2, 1);
            float e3 = __shfl_xor_sync(0xFFFFFFFFu, c3, 1);
            // even lane: row gid,   gates i,f own (c0,c1), g,o from odd (e0,e1)
            // odd lane:  row gid+8, gates g,o own (c2,c3), i,f from even (e2,e3)
            float zi = odd ? e2 : c0;
            float zf = odd ? e3 : c1;
            float zg = odd ? c2 : e0;
            float zo = odd ? c3 : e1;
            int row = wm * 64 + mf * 16 + gid + (odd ? 8 : 0);
            int jl  = wn * 16 + nf * 2 + (tig >> 1);
            float ig = sigm(zi), fg = sigm(zf), gg = tanh_(zg), og = sigm(zo);
            P[row * EPS + jl]  = ig * gg;
            F[row * EPS + jl]  = fg;
            OG[row * EPS + jl] = og;
        }
    __syncthreads();

    // ---- coalesced state update ----
    const bool first = (t == 0);
#pragma unroll
    for (int it = 0; it < 32; it++) {
        int idx = it * 256 + tid;      // 0..8191 = 128 rows x 64 j
        int row = idx >> 6, j = idx & 63;
        size_t g = (size_t)(m0 + row) * HDIM + jblk + j;
        float cold = first ? 0.0f : g_c[g];
        float cnew = F[row * EPS + j] * cold + P[row * EPS + j];
        float h = OG[row * EPS + j] * tanh_(cnew);
        g_c[g]  = cnew;
        hist[g] = h;            // full precision for output
        hdst[g] = tf32r(h);     // rounded for next GEMM
    }
}

// ---------- final transpose: g_hist[t][n*H+j] -> out[(n*H+j)*L + t] ----------
__global__ void finalize(float* __restrict__ out) {
    const int p = blockIdx.x * 256 + threadIdx.x;
    float v[LSTEPS];
#pragma unroll
    for (int t = 0; t < LSTEPS; t++) v[t] = g_hist[t][p];
    float4* o = (float4*)(out + (size_t)p * LSTEPS);
#pragma unroll
    for (int q = 0; q < LSTEPS / 4; q++)
        o[q] = make_float4(v[4 * q], v[4 * q + 1], v[4 * q + 2], v[4 * q + 3]);
}

extern "C" void kernel_launch(void* const* d_in, const int* in_sizes, int n_in,
                              void* d_out, int out_size) {
    const float* h_in = (const float*)d_in[0];
    const float* W    = (const float*)d_in[1];
    const float* b_ih = (const float*)d_in[2];
    const float* b_hh = (const float*)d_in[3];

    cudaFuncSetAttribute(lstm_step, cudaFuncAttributeMaxDynamicSharedMemorySize, SMEM_TOTAL);

    prep_h<<<NBATCH * HDIM / 4 / 256, 256>>>(h_in);
    prep_w<<<4 * HDIM * HDIM / 4 / 256, 256>>>(W);
    prep_bias<<<16, 256>>>(b_ih, b_hh);

    dim3 grid(NBATCH / TM, HDIM / TJ / (TN / TJ / 4));  // 16 x 16
    for (int t = 0; t < LSTEPS; t++) {
        lstm_step<<<dim3(16, 16), 256, SMEM_TOTAL>>>(t);
    }
    finalize<<<NBATCH * HDIM / 256, 256>>>((float*)d_out);
}

// round 4
// speedup vs baseline: 1.5894x; 1.0284x over previous
#include <cuda_runtime.h>
#include <cstdint>

// LSTMDecoder on GB300 (sm_103 ptxas target -> mma.sync tf32 path).
// 48 sequential steps of z = h @ W^T + bias (M=2048, N=4096, K=1024),
// fused i/f/g/o gate epilogue.
// R4: 128x128 CTA tiles, 2 CTAs/SM (regs<=128, smem 97KB), cp.async 3-stage
// pipeline, SW128 swizzle, 32x64 warp tiles, bias folded into acc init,
// shfl-paired gate fusion, contiguous per-step output + final transpose.

#define HDIM   1024
#define NBATCH 2048
#define LSTEPS 48
#define TM     128          // CTA rows (batch)
#define TN     128          // CTA z-cols (= 32 j x 4 gates, interleaved j*4+g)
#define TJ     32
#define BK     32           // K per stage (32 f32 = 128B rows)
#define NSTAGE 3
#define KTILES (HDIM / BK)  // 32

#define SM_BIAS 0                                   // 128 floats
#define SM_PIPE 1024
#define A_BYTES (TM * BK * 4)                       // 16384
#define B_BYTES (TN * BK * 4)                       // 16384
#define STAGE_BYTES (A_BYTES + B_BYTES)             // 32768
#define SMEM_TOTAL (SM_PIPE + NSTAGE * STAGE_BYTES) // 99328 (2 CTAs/SM fit)

#define EPS 33                                      // epilogue j-stride (padded)

#define SWZ(o) ((o) ^ (((o) >> 3) & 0x70))

__device__ float g_h[2][NBATCH * HDIM];          // tf32-rounded h ping-pong
__device__ float g_c[NBATCH * HDIM];             // cell state (fp32)
__device__ float g_Wr[4 * HDIM * HDIM];          // reordered+rounded W: row j*4+g
__device__ float g_biasr[4 * HDIM];              // reordered bias
__device__ float g_hist[LSTEPS][NBATCH * HDIM];  // full-precision h history

// ---------- helpers ----------
__device__ __forceinline__ uint32_t smem_u32(const void* p) {
    uint32_t a;
    asm("{ .reg .u64 t; cvta.to.shared.u64 t, %1; cvt.u32.u64 %0, t; }" : "=r"(a) : "l"(p));
    return a;
}
__device__ __forceinline__ float tf32r(float x) {
    uint32_t u;
    asm("cvt.rna.tf32.f32 %0, %1;" : "=r"(u) : "f"(x));
    return __uint_as_float(u);
}
__device__ __forceinline__ void cpa16(uint32_t dst, const void* src) {
    asm volatile("cp.async.cg.shared.global [%0], [%1], 16;" :: "r"(dst), "l"(src));
}
#define CP_COMMIT() asm volatile("cp.async.commit_group;" ::: "memory")
#define CP_WAIT1()  asm volatile("cp.async.wait_group 1;" ::: "memory")

__device__ __forceinline__ uint32_t lds32(uint32_t a) {
    uint32_t v;
    asm("ld.shared.b32 %0, [%1];" : "=r"(v) : "r"(a));
    return v;
}
__device__ __forceinline__ void mma8(float* c, const uint32_t* a, const uint32_t* b) {
    asm("mma.sync.aligned.m16n8k8.row.col.f32.tf32.tf32.f32 "
        "{%0,%1,%2,%3}, {%4,%5,%6,%7}, {%8,%9}, {%0,%1,%2,%3};"
        : "+f"(c[0]), "+f"(c[1]), "+f"(c[2]), "+f"(c[3])
        : "r"(a[0]), "r"(a[1]), "r"(a[2]), "r"(a[3]), "r"(b[0]), "r"(b[1]));
}
__device__ __forceinline__ float sigm(float x) {
    return __fdividef(1.0f, 1.0f + __expf(-x));
}
__device__ __forceinline__ float tanh_(float x) {
    return __fdividef(2.0f, 1.0f + __expf(-2.0f * x)) - 1.0f;
}

// ---------- prep kernels ----------
__global__ void prep_h(const float* __restrict__ h_in) {
    int i = blockIdx.x * 256 + threadIdx.x;
    float4 v = ((const float4*)h_in)[i];
    v.x = tf32r(v.x); v.y = tf32r(v.y); v.z = tf32r(v.z); v.w = tf32r(v.w);
    ((float4*)g_h[0])[i] = v;
}
__global__ void prep_w(const float* __restrict__ W) {
    int idx = blockIdx.x * 256 + threadIdx.x;  // 4096 rows x 256 float4
    int rn = idx >> 8, k4 = idx & 255;
    int j = rn >> 2, g = rn & 3;
    float4 v = ((const float4*)W)[(size_t)(g * HDIM + j) * (HDIM / 4) + k4];
    v.x = tf32r(v.x); v.y = tf32r(v.y); v.z = tf32r(v.z); v.w = tf32r(v.w);
    ((float4*)g_Wr)[(size_t)rn * (HDIM / 4) + k4] = v;
}
__global__ void prep_bias(const float* __restrict__ bi, const float* __restrict__ bh) {
    int i = blockIdx.x * 256 + threadIdx.x;
    if (i < 4 * HDIM) {
        int j = i >> 2, g = i & 3;
        g_biasr[i] = bi[g * HDIM + j] + bh[g * HDIM + j];
    }
}

// ---------- main step kernel ----------
__global__ __launch_bounds__(256, 2)
void lstm_step(int t) {
    extern __shared__ char smc[];
    float* sbias = (float*)(smc + SM_BIAS);
    const uint32_t smb = smem_u32(smc);

    const int tid = threadIdx.x;
    const int w = tid >> 5, lane = tid & 31;
    const int gid = lane >> 2, tig = lane & 3;
    const int wm = w & 3, wn = w >> 2;          // 4 x 2 warp grid, 32x64 tiles
    const int m0 = blockIdx.x * TM;
    const int n0 = blockIdx.y * TN;
    const int jblk = blockIdx.y * TJ;

    const float* __restrict__ hsrc = g_h[t & 1];
    float* __restrict__ hdst = g_h[(t + 1) & 1];
    float* __restrict__ hist = g_hist[t];

    if (tid < TN) sbias[tid] = g_biasr[n0 + tid];

    auto load_tile = [&](int kt, int s) {
        const uint32_t abase = smb + SM_PIPE + s * STAGE_BYTES;
        const uint32_t bbase = abase + A_BYTES;
        const float* asrc = hsrc + (size_t)m0 * HDIM + kt * BK;
        const float* bsrc = g_Wr + (size_t)n0 * HDIM + kt * BK;
#pragma unroll
        for (int p = 0; p < 4; p++) {           // A: 128 rows x 128B
            int idx = tid + p * 256;
            int row = idx >> 3, ch = idx & 7;
            uint32_t off = (uint32_t)(row * 128 + ch * 16);
            cpa16(abase + SWZ(off), asrc + (size_t)row * HDIM + ch * 4);
        }
#pragma unroll
        for (int p = 0; p < 4; p++) {           // B: 128 rows x 128B
            int idx = tid + p * 256;
            int row = idx >> 3, ch = idx & 7;
            uint32_t off = (uint32_t)(row * 128 + ch * 16);
            cpa16(bbase + SWZ(off), bsrc + (size_t)row * HDIM + ch * 4);
        }
    };

    load_tile(0, 0); CP_COMMIT();
    load_tile(1, 1); CP_COMMIT();
    __syncthreads();  // sbias visible

    // accumulators, bias folded in (cols of c0/c2 = base, c1/c3 = base+1)
    float acc[2][8][4];
#pragma unroll
    for (int mf = 0; mf < 2; mf++)
#pragma unroll
        for (int nf = 0; nf < 8; nf++) {
            int c = wn * 64 + nf * 8 + 2 * tig;
            float b0 = sbias[c], b1 = sbias[c + 1];
            acc[mf][nf][0] = b0; acc[mf][nf][1] = b1;
            acc[mf][nf][2] = b0; acc[mf][nf][3] = b1;
        }

    uint32_t arow[2], brow[8];
#pragma unroll
    for (int mf = 0; mf < 2; mf++) arow[mf] = (uint32_t)(wm * 32 + mf * 16 + gid) * 128;
#pragma unroll
    for (int nf = 0; nf < 8; nf++) brow[nf] = (uint32_t)(wn * 64 + nf * 8 + gid) * 128;
    const uint32_t t4 = (uint32_t)tig * 4;

#pragma unroll 1
    for (int kt = 0; kt < KTILES; kt++) {
        const int s = kt % NSTAGE;
        CP_WAIT1();
        __syncthreads();
        if (kt + 2 < KTILES) load_tile(kt + 2, (kt + 2) % NSTAGE);
        CP_COMMIT();

        const uint32_t aB = smb + SM_PIPE + s * STAGE_BYTES;
        const uint32_t bB = aB + A_BYTES;
#pragma unroll
        for (int kk = 0; kk < 4; kk++) {
            const uint32_t x0 = (uint32_t)((2 * kk) ^ gid) * 16 + t4;
            const uint32_t x1 = (uint32_t)((2 * kk + 1) ^ gid) * 16 + t4;
            uint32_t af[2][4], bf[8][2];
#pragma unroll
            for (int mf = 0; mf < 2; mf++) {
                uint32_t a0 = aB + arow[mf] + x0;
                uint32_t a1 = aB + arow[mf] + x1;
                af[mf][0] = lds32(a0);
                af[mf][1] = lds32(a0 + 1024);   // row +8
                af[mf][2] = lds32(a1);          // k +4
                af[mf][3] = lds32(a1 + 1024);
            }
#pragma unroll
            for (int nf = 0; nf < 8; nf++) {
                bf[nf][0] = lds32(bB + brow[nf] + x0);
                bf[nf][1] = lds32(bB + brow[nf] + x1);
            }
#pragma unroll
            for (int mf = 0; mf < 2; mf++)
#pragma unroll
                for (int nf = 0; nf < 8; nf++)
                    mma8(acc[mf][nf], af[mf], bf[nf]);
        }
    }
    __syncthreads();  // all MMAs done before smem reuse

    // ---- epilogue: shfl-pair gate fusion -> smem staging ----
    float* P  = (float*)(smc + SM_PIPE);           // i*g
    float* F  = P + TM * EPS;                      // f
    float* OG = F + TM * EPS;                      // o
    const int odd = tig & 1;

#pragma unroll
    for (int mf = 0; mf < 2; mf++)
#pragma unroll
        for (int nf = 0; nf < 8; nf++) {
            float c0 = acc[mf][nf][0], c1 = acc[mf][nf][1];
            float c2 = acc[mf][nf][2], c3 = acc[mf][nf][3];
            float e0 = __shfl_xor_sync(0xFFFFFFFFu, c0, 1);
            float e1 = __shfl_xor_sync(0xFFFFFFFFu, c1, 1);
            float e2 = __shfl_xor_sync(0xFFFFFFFFu, c2, 1);
            float e3 = __shfl_xor_sync(0xFFFFFFFFu, c3, 1);
            // even lane: row gid,   gates i,f own (c0,c1), g,o from odd (e0,e1)
            // odd lane:  row gid+8, gates g,o own (c2,c3), i,f from even (e2,e3)
            float zi = odd ? e2 : c0;
            float zf = odd ? e3 : c1;
            float zg = odd ? c2 : e0;
            float zo = odd ? c3 : e1;
            int row = wm * 32 + mf * 16 + gid + (odd ? 8 : 0);
            int jl  = wn * 16 + nf * 2 + (tig >> 1);
            float ig = sigm(zi), fg = sigm(zf), gg = tanh_(zg), og = sigm(zo);
            P[row * EPS + jl]  = ig * gg;
            F[row * EPS + jl]  = fg;
            OG[row * EPS + jl] = og;
        }
    __syncthreads();

    // ---- coalesced state update ----
    const bool first = (t == 0);
#pragma unroll
    for (int it = 0; it < (TM * TJ) / 256; it++) {
        int idx = it * 256 + tid;      // 0..4095 = 128 rows x 32 j
        int row = idx >> 5, j = idx & 31;
        size_t g = (size_t)(m0 + row) * HDIM + jblk + j;
        float cold = first ? 0.0f : g_c[g];
        float cnew = F[row * EPS + j] * cold + P[row * EPS + j];
        float h = OG[row * EPS + j] * tanh_(cnew);
        g_c[g]  = cnew;
        hist[g] = h;            // full precision for output
        hdst[g] = tf32r(h);     // rounded for next GEMM
    }
}

// ---------- final transpose: g_hist[t][n*H+j] -> out[(n*H+j)*L + t] ----------
__global__ void finalize(float* __restrict__ out) {
    const int p = blockIdx.x * 256 + threadIdx.x;
    float v[LSTEPS];
#pragma unroll
    for (int t = 0; t < LSTEPS; t++) v[t] = g_hist[t][p];
    float4* o = (float4*)(out + (size_t)p * LSTEPS);
#pragma unroll
    for (int q = 0; q < LSTEPS / 4; q++)
        o[q] = make_float4(v[4 * q], v[4 * q + 1], v[4 * q + 2], v[4 * q + 3]);
}

extern "C" void kernel_launch(void* const* d_in, const int* in_sizes, int n_in,
                              void* d_out, int out_size) {
    const float* h_in = (const float*)d_in[0];
    const float* W    = (const float*)d_in[1];
    const float* b_ih = (const float*)d_in[2];
    const float* b_hh = (const float*)d_in[3];

    cudaFuncSetAttribute(lstm_step, cudaFuncAttributeMaxDynamicSharedMemorySize, SMEM_TOTAL);

    prep_h<<<NBATCH * HDIM / 4 / 256, 256>>>(h_in);
    prep_w<<<4 * HDIM * HDIM / 4 / 256, 256>>>(W);
    prep_bias<<<16, 256>>>(b_ih, b_hh);

    for (int t = 0; t < LSTEPS; t++) {
        lstm_step<<<dim3(NBATCH / TM, 4 * HDIM / TN), 256, SMEM_TOTAL>>>(t);
    }
    finalize<<<NBATCH * HDIM / 256, 256>>>((float*)d_out);
}

// round 5
// speedup vs baseline: 2.7332x; 1.7197x over previous
#include <cuda_runtime.h>
#include <cuda_fp16.h>
#include <cstdint>

// LSTMDecoder on GB300 (sm_103 ptxas -> mma.sync path; tcgen05 unavailable).
// 48 sequential steps of z = h @ W^T + bias (M=2048, N=4096, K=1024),
// fused i/f/g/o gate epilogue.
// R5: fp16 m16n8k16 MMA (2x MAC rate vs tf32, same 10-bit mantissa),
// BK=64 (16 k-tiles/step, halved syncs), 128x128 CTA tiles, 2 CTAs/SM,
// cp.async 3-stage pipeline, SW128 swizzle, shfl-paired gate fusion,
// contiguous per-step output + final transpose.

#define HDIM   1024
#define NBATCH 2048
#define LSTEPS 48
#define TM     128          // CTA rows (batch)
#define TN     128          // CTA z-cols (= 32 j x 4 gates, interleaved j*4+g)
#define TJ     32
#define BK     64           // K per stage (64 fp16 = 128B rows)
#define NSTAGE 3
#define KTILES (HDIM / BK)  // 16

#define SM_BIAS 0                                   // 128 floats
#define SM_PIPE 1024
#define A_BYTES (TM * BK * 2)                       // 16384
#define B_BYTES (TN * BK * 2)                       // 16384
#define STAGE_BYTES (A_BYTES + B_BYTES)             // 32768
#define SMEM_TOTAL (SM_PIPE + NSTAGE * STAGE_BYTES) // 99328 (2 CTAs/SM)

#define EPS 33                                      // epilogue j-stride (padded)

#define SWZ(o) ((o) ^ (((o) >> 3) & 0x70))

__device__ __half g_h[2][NBATCH * HDIM];         // fp16 h ping-pong
__device__ float  g_c[NBATCH * HDIM];            // cell state (fp32)
__device__ __half g_Wr[4 * HDIM * HDIM];         // reordered fp16 W: row j*4+g
__device__ float  g_biasr[4 * HDIM];             // reordered bias
__device__ float  g_hist[LSTEPS][NBATCH * HDIM]; // full-precision h history

// ---------- helpers ----------
__device__ __forceinline__ uint32_t smem_u32(const void* p) {
    uint32_t a;
    asm("{ .reg .u64 t; cvta.to.shared.u64 t, %1; cvt.u32.u64 %0, t; }" : "=r"(a) : "l"(p));
    return a;
}
__device__ __forceinline__ void cpa16(uint32_t dst, const void* src) {
    asm volatile("cp.async.cg.shared.global [%0], [%1], 16;" :: "r"(dst), "l"(src));
}
#define CP_COMMIT() asm volatile("cp.async.commit_group;" ::: "memory")
#define CP_WAIT1()  asm volatile("cp.async.wait_group 1;" ::: "memory")

__device__ __forceinline__ uint32_t lds32(uint32_t a) {
    uint32_t v;
    asm("ld.shared.b32 %0, [%1];" : "=r"(v) : "r"(a));
    return v;
}
__device__ __forceinline__ void mma16(float* c, const uint32_t* a, const uint32_t* b) {
    asm("mma.sync.aligned.m16n8k16.row.col.f32.f16.f16.f32 "
        "{%0,%1,%2,%3}, {%4,%5,%6,%7}, {%8,%9}, {%0,%1,%2,%3};"
        : "+f"(c[0]), "+f"(c[1]), "+f"(c[2]), "+f"(c[3])
        : "r"(a[0]), "r"(a[1]), "r"(a[2]), "r"(a[3]), "r"(b[0]), "r"(b[1]));
}
__device__ __forceinline__ float sigm(float x) {
    return __fdividef(1.0f, 1.0f + __expf(-x));
}
__device__ __forceinline__ float tanh_(float x) {
    return __fdividef(2.0f, 1.0f + __expf(-2.0f * x)) - 1.0f;
}

// ---------- prep kernels ----------
__global__ void prep_h(const float* __restrict__ h_in) {
    int i = blockIdx.x * 256 + threadIdx.x;     // float4 index
    float4 v = ((const float4*)h_in)[i];
    __half2 lo = __floats2half2_rn(v.x, v.y);
    __half2 hi = __floats2half2_rn(v.z, v.w);
    ((uint2*)g_h[0])[i] = make_uint2(*(uint32_t*)&lo, *(uint32_t*)&hi);
}
__global__ void prep_w(const float* __restrict__ W) {
    int idx = blockIdx.x * 256 + threadIdx.x;   // 4096 rows x 256 float4
    int rn = idx >> 8, k4 = idx & 255;
    int j = rn >> 2, g = rn & 3;
    float4 v = ((const float4*)W)[(size_t)(g * HDIM + j) * (HDIM / 4) + k4];
    __half2 lo = __floats2half2_rn(v.x, v.y);
    __half2 hi = __floats2half2_rn(v.z, v.w);
    ((uint2*)g_Wr)[(size_t)rn * (HDIM / 4) + k4] =
        make_uint2(*(uint32_t*)&lo, *(uint32_t*)&hi);
}
__global__ void prep_bias(const float* __restrict__ bi, const float* __restrict__ bh) {
    int i = blockIdx.x * 256 + threadIdx.x;
    if (i < 4 * HDIM) {
        int j = i >> 2, g = i & 3;
        g_biasr[i] = bi[g * HDIM + j] + bh[g * HDIM + j];
    }
}

// ---------- main step kernel ----------
__global__ __launch_bounds__(256, 2)
void lstm_step(int t) {
    extern __shared__ char smc[];
    float* sbias = (float*)(smc + SM_BIAS);
    const uint32_t smb = smem_u32(smc);

    const int tid = threadIdx.x;
    const int w = tid >> 5, lane = tid & 31;
    const int gid = lane >> 2, tig = lane & 3;
    const int wm = w & 3, wn = w >> 2;          // 4 x 2 warp grid, 32x64 tiles
    const int m0 = blockIdx.x * TM;
    const int n0 = blockIdx.y * TN;
    const int jblk = blockIdx.y * TJ;

    const __half* __restrict__ hsrc = g_h[t & 1];
    __half* __restrict__ hdst = g_h[(t + 1) & 1];
    float* __restrict__ hist = g_hist[t];

    if (tid < TN) sbias[tid] = g_biasr[n0 + tid];

    auto load_tile = [&](int kt, int s) {
        const uint32_t abase = smb + SM_PIPE + s * STAGE_BYTES;
        const uint32_t bbase = abase + A_BYTES;
        const __half* asrc = hsrc + (size_t)m0 * HDIM + kt * BK;
        const __half* bsrc = g_Wr + (size_t)n0 * HDIM + kt * BK;
#pragma unroll
        for (int p = 0; p < 4; p++) {           // A: 128 rows x 128B
            int idx = tid + p * 256;
            int row = idx >> 3, ch = idx & 7;
            uint32_t off = (uint32_t)(row * 128 + ch * 16);
            cpa16(abase + SWZ(off), asrc + (size_t)row * HDIM + ch * 8);
        }
#pragma unroll
        for (int p = 0; p < 4; p++) {           // B: 128 rows x 128B
            int idx = tid + p * 256;
            int row = idx >> 3, ch = idx & 7;
            uint32_t off = (uint32_t)(row * 128 + ch * 16);
            cpa16(bbase + SWZ(off), bsrc + (size_t)row * HDIM + ch * 8);
        }
    };

    load_tile(0, 0); CP_COMMIT();
    load_tile(1, 1); CP_COMMIT();
    __syncthreads();  // sbias visible

    // accumulators, bias folded in (cols of c0/c2 = base, c1/c3 = base+1)
    float acc[2][8][4];
#pragma unroll
    for (int mf = 0; mf < 2; mf++)
#pragma unroll
        for (int nf = 0; nf < 8; nf++) {
            int c = wn * 64 + nf * 8 + 2 * tig;
            float b0 = sbias[c], b1 = sbias[c + 1];
            acc[mf][nf][0] = b0; acc[mf][nf][1] = b1;
            acc[mf][nf][2] = b0; acc[mf][nf][3] = b1;
        }

    // smem row byte offsets (row stride 128B; +8 rows = +1024B, swizzle-safe)
    uint32_t arow[2], brow[8];
#pragma unroll
    for (int mf = 0; mf < 2; mf++) arow[mf] = (uint32_t)(wm * 32 + mf * 16 + gid) * 128;
#pragma unroll
    for (int nf = 0; nf < 8; nf++) brow[nf] = (uint32_t)(wn * 64 + nf * 8 + gid) * 128;
    const uint32_t t4 = (uint32_t)tig * 4;

#pragma unroll 1
    for (int kt = 0; kt < KTILES; kt++) {
        const int s = kt % NSTAGE;
        CP_WAIT1();
        __syncthreads();
        if (kt + 2 < KTILES) load_tile(kt + 2, (kt + 2) % NSTAGE);
        CP_COMMIT();

        const uint32_t aB = smb + SM_PIPE + s * STAGE_BYTES;
        const uint32_t bB = aB + A_BYTES;
#pragma unroll
        for (int kk = 0; kk < 4; kk++) {        // 4 x k16 = 64 K elems
            // chunk (2kk) and (2kk+1), XOR-swizzled by row&7 (= gid)
            const uint32_t x0 = (uint32_t)((2 * kk) ^ gid) * 16 + t4;
            const uint32_t x1 = (uint32_t)((2 * kk + 1) ^ gid) * 16 + t4;
            uint32_t af[2][4], bf[8][2];
#pragma unroll
            for (int mf = 0; mf < 2; mf++) {
                uint32_t a0 = aB + arow[mf] + x0;
                uint32_t a1 = aB + arow[mf] + x1;
                af[mf][0] = lds32(a0);          // row gid,   k 2tig..+1
                af[mf][1] = lds32(a0 + 1024);   // row gid+8
                af[mf][2] = lds32(a1);          // row gid,   k 2tig+8..+9
                af[mf][3] = lds32(a1 + 1024);
            }
#pragma unroll
            for (int nf = 0; nf < 8; nf++) {
                bf[nf][0] = lds32(bB + brow[nf] + x0);
                bf[nf][1] = lds32(bB + brow[nf] + x1);
            }
#pragma unroll
            for (int mf = 0; mf < 2; mf++)
#pragma unroll
                for (int nf = 0; nf < 8; nf++)
                    mma16(acc[mf][nf], af[mf], bf[nf]);
        }
    }
    __syncthreads();  // all MMAs done before smem reuse

    // ---- epilogue: shfl-pair gate fusion -> smem staging ----
    float* P  = (float*)(smc + SM_PIPE);           // i*g
    float* F  = P + TM * EPS;                      // f
    float* OG = F + TM * EPS;                      // o
    const int odd = tig & 1;

#pragma unroll
    for (int mf = 0; mf < 2; mf++)
#pragma unroll
        for (int nf = 0; nf < 8; nf++) {
            float c0 = acc[mf][nf][0], c1 = acc[mf][nf][1];
            float c2 = acc[mf][nf][2], c3 = acc[mf][nf][3];
            float e0 = __shfl_xor_sync(0xFFFFFFFFu, c0, 1);
            float e1 = __shfl_xor_sync(0xFFFFFFFFu, c1, 1);
            float e2 = __shfl_xor_sync(0xFFFFFFFFu, c2, 1);
            float e3 = __shfl_xor_sync(0xFFFFFFFFu, c3, 1);
            // even lane: row gid,   gates i,f own (c0,c1), g,o from odd (e0,e1)
            // odd lane:  row gid+8, gates g,o own (c2,c3), i,f from even (e2,e3)
            float zi = odd ? e2 : c0;
            float zf = odd ? e3 : c1;
            float zg = odd ? c2 : e0;
            float zo = odd ? c3 : e1;
            int row = wm * 32 + mf * 16 + gid + (odd ? 8 : 0);
            int jl  = wn * 16 + nf * 2 + (tig >> 1);
            float ig = sigm(zi), fg = sigm(zf), gg = tanh_(zg), og = sigm(zo);
            P[row * EPS + jl]  = ig * gg;
            F[row * EPS + jl]  = fg;
            OG[row * EPS + jl] = og;
        }
    __syncthreads();

    // ---- coalesced state update ----
    const bool first = (t == 0);
#pragma unroll
    for (int it = 0; it < (TM * TJ) / 256; it++) {
        int idx = it * 256 + tid;      // 128 rows x 32 j
        int row = idx >> 5, j = idx & 31;
        size_t g = (size_t)(m0 + row) * HDIM + jblk + j;
        float cold = first ? 0.0f : g_c[g];
        float cnew = F[row * EPS + j] * cold + P[row * EPS + j];
        float h = OG[row * EPS + j] * tanh_(cnew);
        g_c[g]  = cnew;
        hist[g] = h;                    // full precision for output
        hdst[g] = __float2half_rn(h);   // fp16 for next GEMM
    }
}

// ---------- final transpose: g_hist[t][n*H+j] -> out[(n*H+j)*L + t] ----------
__global__ void finalize(float* __restrict__ out) {
    const int p = blockIdx.x * 256 + threadIdx.x;
    float v[LSTEPS];
#pragma unroll
    for (int t = 0; t < LSTEPS; t++) v[t] = g_hist[t][p];
    float4* o = (float4*)(out + (size_t)p * LSTEPS);
#pragma unroll
    for (int q = 0; q < LSTEPS / 4; q++)
        o[q] = make_float4(v[4 * q], v[4 * q + 1], v[4 * q + 2], v[4 * q + 3]);
}

extern "C" void kernel_launch(void* const* d_in, const int* in_sizes, int n_in,
                              void* d_out, int out_size) {
    const float* h_in = (const float*)d_in[0];
    const float* W    = (const float*)d_in[1];
    const float* b_ih = (const float*)d_in[2];
    const float* b_hh = (const float*)d_in[3];

    cudaFuncSetAttribute(lstm_step, cudaFuncAttributeMaxDynamicSharedMemorySize, SMEM_TOTAL);

    prep_h<<<NBATCH * HDIM / 4 / 256, 256>>>(h_in);
    prep_w<<<4 * HDIM * HDIM / 4 / 256, 256>>>(W);
    prep_bias<<<16, 256>>>(b_ih, b_hh);

    for (int t = 0; t < LSTEPS; t++) {
        lstm_step<<<dim3(NBATCH / TM, 4 * HDIM / TN), 256, SMEM_TOTAL>>>(t);
    }
    finalize<<<NBATCH * HDIM / 256, 256>>>((float*)d_out);
}

// round 6
// speedup vs baseline: 2.9077x; 1.0638x over previous
#include <cuda_runtime.h>
#include <cuda_fp16.h>
#include <cstdint>

// LSTMDecoder on GB300 (sm_103 ptxas -> mma.sync path; tcgen05 unavailable).
// 48 sequential steps of z = h @ W^T + bias (M=2048, N=4096, K=1024),
// fused i/f/g/o gate epilogue.
// R6: fp16 m16n8k16 MMA + ldmatrix.x4 fragment loads (96 LDS -> 24 ldmatrix
// per warp per k-tile, XOR-immediate swizzle addressing), BK=64, 128x128 CTA
// tiles, 2 CTAs/SM, cp.async 3-stage pipeline, shfl-paired gate fusion,
// contiguous per-step output + final transpose.

#define HDIM   1024
#define NBATCH 2048
#define LSTEPS 48
#define TM     128          // CTA rows (batch)
#define TN     128          // CTA z-cols (= 32 j x 4 gates, interleaved j*4+g)
#define TJ     32
#define BK     64           // K per stage (64 fp16 = 128B rows)
#define NSTAGE 3
#define KTILES (HDIM / BK)  // 16

#define SM_BIAS 0                                   // 128 floats
#define SM_PIPE 1024
#define A_BYTES (TM * BK * 2)                       // 16384
#define B_BYTES (TN * BK * 2)                       // 16384
#define STAGE_BYTES (A_BYTES + B_BYTES)             // 32768
#define SMEM_TOTAL (SM_PIPE + NSTAGE * STAGE_BYTES) // 99328 (2 CTAs/SM)

#define EPS 33                                      // epilogue j-stride (padded)

#define SWZ(o) ((o) ^ (((o) >> 3) & 0x70))

__device__ __half g_h[2][NBATCH * HDIM];         // fp16 h ping-pong
__device__ float  g_c[NBATCH * HDIM];            // cell state (fp32)
__device__ __half g_Wr[4 * HDIM * HDIM];         // reordered fp16 W: row j*4+g
__device__ float  g_biasr[4 * HDIM];             // reordered bias
__device__ float  g_hist[LSTEPS][NBATCH * HDIM]; // full-precision h history

// ---------- helpers ----------
__device__ __forceinline__ uint32_t smem_u32(const void* p) {
    uint32_t a;
    asm("{ .reg .u64 t; cvta.to.shared.u64 t, %1; cvt.u32.u64 %0, t; }" : "=r"(a) : "l"(p));
    return a;
}
__device__ __forceinline__ void cpa16(uint32_t dst, const void* src) {
    asm volatile("cp.async.cg.shared.global [%0], [%1], 16;" :: "r"(dst), "l"(src));
}
#define CP_COMMIT() asm volatile("cp.async.commit_group;" ::: "memory")
#define CP_WAIT1()  asm volatile("cp.async.wait_group 1;" ::: "memory")

__device__ __forceinline__ void ldm_x4(uint32_t* r, uint32_t addr) {
    asm volatile("ldmatrix.sync.aligned.m8n8.x4.shared.b16 {%0,%1,%2,%3}, [%4];"
                 : "=r"(r[0]), "=r"(r[1]), "=r"(r[2]), "=r"(r[3]) : "r"(addr));
}
__device__ __forceinline__ void mma16(float* c, const uint32_t* a, const uint32_t* b) {
    asm("mma.sync.aligned.m16n8k16.row.col.f32.f16.f16.f32 "
        "{%0,%1,%2,%3}, {%4,%5,%6,%7}, {%8,%9}, {%0,%1,%2,%3};"
        : "+f"(c[0]), "+f"(c[1]), "+f"(c[2]), "+f"(c[3])
        : "r"(a[0]), "r"(a[1]), "r"(a[2]), "r"(a[3]), "r"(b[0]), "r"(b[1]));
}
__device__ __forceinline__ float sigm(float x) {
    return __fdividef(1.0f, 1.0f + __expf(-x));
}
__device__ __forceinline__ float tanh_(float x) {
    return __fdividef(2.0f, 1.0f + __expf(-2.0f * x)) - 1.0f;
}

// ---------- prep kernels ----------
__global__ void prep_h(const float* __restrict__ h_in) {
    int i = blockIdx.x * 256 + threadIdx.x;     // float4 index
    float4 v = ((const float4*)h_in)[i];
    __half2 lo = __floats2half2_rn(v.x, v.y);
    __half2 hi = __floats2half2_rn(v.z, v.w);
    ((uint2*)g_h[0])[i] = make_uint2(*(uint32_t*)&lo, *(uint32_t*)&hi);
}
__global__ void prep_w(const float* __restrict__ W) {
    int idx = blockIdx.x * 256 + threadIdx.x;   // 4096 rows x 256 float4
    int rn = idx >> 8, k4 = idx & 255;
    int j = rn >> 2, g = rn & 3;
    float4 v = ((const float4*)W)[(size_t)(g * HDIM + j) * (HDIM / 4) + k4];
    __half2 lo = __floats2half2_rn(v.x, v.y);
    __half2 hi = __floats2half2_rn(v.z, v.w);
    ((uint2*)g_Wr)[(size_t)rn * (HDIM / 4) + k4] =
        make_uint2(*(uint32_t*)&lo, *(uint32_t*)&hi);
}
__global__ void prep_bias(const float* __restrict__ bi, const float* __restrict__ bh) {
    int i = blockIdx.x * 256 + threadIdx.x;
    if (i < 4 * HDIM) {
        int j = i >> 2, g = i & 3;
        g_biasr[i] = bi[g * HDIM + j] + bh[g * HDIM + j];
    }
}

// ---------- main step kernel ----------
__global__ __launch_bounds__(256, 2)
void lstm_step(int t) {
    extern __shared__ char smc[];
    float* sbias = (float*)(smc + SM_BIAS);
    const uint32_t smb = smem_u32(smc);

    const int tid = threadIdx.x;
    const int w = tid >> 5, lane = tid & 31;
    const int gid = lane >> 2, tig = lane & 3;
    const int wm = w & 3, wn = w >> 2;          // 4 x 2 warp grid, 32x64 tiles
    const int m0 = blockIdx.x * TM;
    const int n0 = blockIdx.y * TN;
    const int jblk = blockIdx.y * TJ;

    const __half* __restrict__ hsrc = g_h[t & 1];
    __half* __restrict__ hdst = g_h[(t + 1) & 1];
    float* __restrict__ hist = g_hist[t];

    if (tid < TN) sbias[tid] = g_biasr[n0 + tid];

    auto load_tile = [&](int kt, int s) {
        const uint32_t abase = smb + SM_PIPE + s * STAGE_BYTES;
        const uint32_t bbase = abase + A_BYTES;
        const __half* asrc = hsrc + (size_t)m0 * HDIM + kt * BK;
        const __half* bsrc = g_Wr + (size_t)n0 * HDIM + kt * BK;
#pragma unroll
        for (int p = 0; p < 4; p++) {           // A: 128 rows x 128B
            int idx = tid + p * 256;
            int row = idx >> 3, ch = idx & 7;
            uint32_t off = (uint32_t)(row * 128 + ch * 16);
            cpa16(abase + SWZ(off), asrc + (size_t)row * HDIM + ch * 8);
        }
#pragma unroll
        for (int p = 0; p < 4; p++) {           // B: 128 rows x 128B
            int idx = tid + p * 256;
            int row = idx >> 3, ch = idx & 7;
            uint32_t off = (uint32_t)(row * 128 + ch * 16);
            cpa16(bbase + SWZ(off), bsrc + (size_t)row * HDIM + ch * 8);
        }
    };

    load_tile(0, 0); CP_COMMIT();
    load_tile(1, 1); CP_COMMIT();
    __syncthreads();  // sbias visible

    // accumulators, bias folded in (cols of c0/c2 = base, c1/c3 = base+1)
    float acc[2][8][4];
#pragma unroll
    for (int mf = 0; mf < 2; mf++)
#pragma unroll
        for (int nf = 0; nf < 8; nf++) {
            int c = wn * 64 + nf * 8 + 2 * tig;
            float b0 = sbias[c], b1 = sbias[c + 1];
            acc[mf][nf][0] = b0; acc[mf][nf][1] = b1;
            acc[mf][nf][2] = b0; acc[mf][nf][3] = b1;
        }

    // ---- ldmatrix lane addressing (relative to stage base) ----
    // addr(kk) = (stage_base + rel0) ^ (kk << 5)   [swizzle bits 4-6, carry-free]
    const int rit = lane & 7;          // row-within-8 (= row & 7 for all tiles)
    const int tg  = lane >> 3;         // ldmatrix tile group 0..3
    // A matrices per mf: [m0-7 klo, m8-15 klo, m0-7 khi, m8-15 khi]
    uint32_t ra[2];
#pragma unroll
    for (int mf = 0; mf < 2; mf++) {
        int arow = wm * 32 + mf * 16 + (tg & 1) * 8 + rit;
        ra[mf] = SM_PIPE + (uint32_t)arow * 128 + ((uint32_t)((tg >> 1) ^ rit) << 4);
    }
    // B matrices per pair p (nf=2p,2p+1): [n(2p) klo, n(2p) khi, n(2p+1) klo, n(2p+1) khi]
    uint32_t rb[4];
#pragma unroll
    for (int p = 0; p < 4; p++) {
        int brow = wn * 64 + (2 * p + (tg >> 1)) * 8 + rit;
        rb[p] = SM_PIPE + A_BYTES + (uint32_t)brow * 128 +
                ((uint32_t)((tg & 1) ^ rit) << 4);
    }

#pragma unroll 1
    for (int kt = 0; kt < KTILES; kt++) {
        const int s = kt % NSTAGE;
        CP_WAIT1();
        __syncthreads();
        if (kt + 2 < KTILES) load_tile(kt + 2, (kt + 2) % NSTAGE);
        CP_COMMIT();

        const uint32_t sb = smb + (uint32_t)s * STAGE_BYTES;
        const uint32_t a0 = sb + ra[0], a1 = sb + ra[1];
        const uint32_t b0 = sb + rb[0], b1 = sb + rb[1];
        const uint32_t b2 = sb + rb[2], b3 = sb + rb[3];
#pragma unroll
        for (int kk = 0; kk < 4; kk++) {        // 4 x k16 = 64 K elems
            const uint32_t x = (uint32_t)kk << 5;
            uint32_t af[2][4], bf[4][4];        // bf[p] = {n2p:b0,b1, n2p+1:b0,b1}
            ldm_x4(af[0], a0 ^ x);
            ldm_x4(af[1], a1 ^ x);
            ldm_x4(bf[0], b0 ^ x);
            ldm_x4(bf[1], b1 ^ x);
            ldm_x4(bf[2], b2 ^ x);
            ldm_x4(bf[3], b3 ^ x);
#pragma unroll
            for (int mf = 0; mf < 2; mf++)
#pragma unroll
                for (int nf = 0; nf < 8; nf++)
                    mma16(acc[mf][nf], af[mf], &bf[nf >> 1][(nf & 1) * 2]);
        }
    }
    __syncthreads();  // all MMAs done before smem reuse

    // ---- epilogue: shfl-pair gate fusion -> smem staging ----
    float* P  = (float*)(smc + SM_PIPE);           // i*g
    float* F  = P + TM * EPS;                      // f
    float* OG = F + TM * EPS;                      // o
    const int odd = tig & 1;

#pragma unroll
    for (int mf = 0; mf < 2; mf++)
#pragma unroll
        for (int nf = 0; nf < 8; nf++) {
            float c0 = acc[mf][nf][0], c1 = acc[mf][nf][1];
            float c2 = acc[mf][nf][2], c3 = acc[mf][nf][3];
            float e0 = __shfl_xor_sync(0xFFFFFFFFu, c0, 1);
            float e1 = __shfl_xor_sync(0xFFFFFFFFu, c1, 1);
            float e2 = __shfl_xor_sync(0xFFFFFFFFu, c2, 1);
            float e3 = __shfl_xor_sync(0xFFFFFFFFu, c3, 1);
            // even lane: row gid,   gates i,f own (c0,c1), g,o from odd (e0,e1)
            // odd lane:  row gid+8, gates g,o own (c2,c3), i,f from even (e2,e3)
            float zi = odd ? e2 : c0;
            float zf = odd ? e3 : c1;
            float zg = odd ? c2 : e0;
            float zo = odd ? c3 : e1;
            int row = wm * 32 + mf * 16 + gid + (odd ? 8 : 0);
            int jl  = wn * 16 + nf * 2 + (tig >> 1);
            float ig = sigm(zi), fg = sigm(zf), gg = tanh_(zg), og = sigm(zo);
            P[row * EPS + jl]  = ig * gg;
            F[row * EPS + jl]  = fg;
            OG[row * EPS + jl] = og;
        }
    __syncthreads();

    // ---- coalesced state update ----
    const bool first = (t == 0);
#pragma unroll
    for (int it = 0; it < (TM * TJ) / 256; it++) {
        int idx = it * 256 + tid;      // 128 rows x 32 j
        int row = idx >> 5, j = idx & 31;
        size_t g = (size_t)(m0 + row) * HDIM + jblk + j;
        float cold = first ? 0.0f : g_c[g];
        float cnew = F[row * EPS + j] * cold + P[row * EPS + j];
        float h = OG[row * EPS + j] * tanh_(cnew);
        g_c[g]  = cnew;
        hist[g] = h;                    // full precision for output
        hdst[g] = __float2half_rn(h);   // fp16 for next GEMM
    }
}

// ---------- final transpose: g_hist[t][n*H+j] -> out[(n*H+j)*L + t] ----------
__global__ void finalize(float* __restrict__ out) {
    const int p = blockIdx.x * 256 + threadIdx.x;
    float v[LSTEPS];
#pragma unroll
    for (int t = 0; t < LSTEPS; t++) v[t] = g_hist[t][p];
    float4* o = (float4*)(out + (size_t)p * LSTEPS);
#pragma unroll
    for (int q = 0; q < LSTEPS / 4; q++)
        o[q] = make_float4(v[4 * q], v[4 * q + 1], v[4 * q + 2], v[4 * q + 3]);
}

extern "C" void kernel_launch(void* const* d_in, const int* in_sizes, int n_in,
                              void* d_out, int out_size) {
    const float* h_in = (const float*)d_in[0];
    const float* W    = (const float*)d_in[1];
    const float* b_ih = (const float*)d_in[2];
    const float* b_hh = (const float*)d_in[3];

    cudaFuncSetAttribute(lstm_step, cudaFuncAttributeMaxDynamicSharedMemorySize, SMEM_TOTAL);

    prep_h<<<NBATCH * HDIM / 4 / 256, 256>>>(h_in);
    prep_w<<<4 * HDIM * HDIM / 4 / 256, 256>>>(W);
    prep_bias<<<16, 256>>>(b_ih, b_hh);

    for (int t = 0; t < LSTEPS; t++) {
        lstm_step<<<dim3(NBATCH / TM, 4 * HDIM / TN), 256, SMEM_TOTAL>>>(t);
    }
    finalize<<<NBATCH * HDIM / 256, 256>>>((float*)d_out);
}